// round 3
// baseline (speedup 1.0000x reference)
#include <cuda_runtime.h>
#include <math.h>

// ---------------- scratch (no allocations allowed) ----------------
__device__ float g_ws[4 * 49];   // fused dot products: [sigx|sigy|op|rho] x 49 patch-positions

// ---------------- packed f32x2 FMA helpers (sm_103a FFMA2) ----------------
__device__ __forceinline__ void fma2(unsigned long long& acc, unsigned long long xy,
                                     unsigned long long w) {
    asm("fma.rn.f32x2 %0, %1, %2, %0;" : "+l"(acc) : "l"(xy), "l"(w));
}
__device__ __forceinline__ unsigned long long pack2(float lo, float hi) {
    unsigned long long r;
    asm("mov.b64 %0, {%1, %2};" : "=l"(r) : "f"(lo), "f"(hi));
    return r;
}

// ---------------- kernel 0: zero the ws accumulators ----------------
__global__ void k_zero() {
    int t = threadIdx.x;
    if (t < 196) g_ws[t] = 0.0f;
}

// ---------------- kernel 1: logits -> patch-position sums, fused sigma dots ----------------
// grid = 1600 (one plane b*100+n per block), block = 224 threads.
__global__ void __launch_bounds__(224) k_reduce(const float* __restrict__ logits,
                                                const float* __restrict__ sigx,
                                                const float* __restrict__ sigy,
                                                const float* __restrict__ opac,
                                                const float* __restrict__ rho) {
    const int plane = blockIdx.x;                 // b*100 + n
    const int n = plane % 100;
    const float4* __restrict__ base4 =
        (const float4*)(logits + (size_t)plane * 12544);
    const int t = threadIdx.x;
    const int c4 = t % 28;
    const int rb = t / 28;

    __shared__ float s[224 * 29];   // [t][28] padded to 29 (conflict-free)
    __shared__ float s2[784];       // [c4][28]

    float acc[7][4];
#pragma unroll
    for (int i = 0; i < 7; i++)
#pragma unroll
        for (int j = 0; j < 4; j++) acc[i][j] = 0.0f;

#pragma unroll
    for (int k = 0; k < 14; k++) {
        const int r = rb * 14 + k;
        const float4 v = base4[r * 28 + c4];
        const int ph = k % 7;
        acc[ph][0] += v.x;
        acc[ph][1] += v.y;
        acc[ph][2] += v.z;
        acc[ph][3] += v.w;
    }

#pragma unroll
    for (int ph = 0; ph < 7; ph++)
#pragma unroll
        for (int j = 0; j < 4; j++) s[t * 29 + ph * 4 + j] = acc[ph][j];
    __syncthreads();

    // reduce over the 8 row-bands: s2[c4*28 + i] = sum_rb s[(rb*28+c4)*29 + i]
#pragma unroll
    for (int u = 0; u < 4; u++) {
        const int id = u * 224 + t;
        if (id < 784) {
            const int cc4 = id / 28;
            const int i = id % 28;
            float sum = 0.0f;
#pragma unroll
            for (int r8 = 0; r8 < 8; r8++) sum += s[(r8 * 28 + cc4) * 29 + i];
            s2[cc4 * 28 + i] = sum;
        }
    }
    __syncthreads();

    // fold column groups into the 49 (row-phase, col-phase) bins; fuse n-dots
    if (t < 49) {
        const int rp = t / 7, cp = t % 7;
        float sum = 0.0f;
#pragma unroll
        for (int cc4 = 0; cc4 < 28; cc4++) {
            const int j = (cp + 112 - 4 * cc4) % 7;  // which of the 4 lanes maps to cp
            if (j < 4) sum += s2[cc4 * 28 + rp * 4 + j];
        }
        atomicAdd(&g_ws[t],       sum * sigx[n]);
        atomicAdd(&g_ws[49 + t],  sum * sigy[n]);
        atomicAdd(&g_ws[98 + t],  sum * opac[n]);
        atomicAdd(&g_ws[147 + t], sum * rho[n]);
    }
}

// ---------------- kernel 2: fused params + splat-apply ----------------
// grid = 512 (bc=128 x quarter-bands of 28 rows), block = 128 threads.
// Compute: warp = qq (q-quarter), lane = patch-pair index -> patches 2*lane, 2*lane+1.
__global__ void __launch_bounds__(128) k_apply(const float* __restrict__ inp,
                                               float* __restrict__ out) {
    __shared__ __align__(16) float sInT[49 * 66];       // [p][patch], stride 66 (even)
    __shared__ __align__(16) float2 sW2[49 * 50];       // W[p][q] duplicated pairs
    __shared__ float kp[49 * 49];                        // scratch Gaussian kernels

    const int blk = blockIdx.x;
    const int bc = blk >> 2;          // b*8 + c
    const int quarter = blk & 3;
    const int b = bc >> 3, c = bc & 7;
    const float* src = inp + ((size_t)b * 64 + c) * 12544 + (size_t)quarter * 28 * 112;
    float* dst = out + (size_t)bc * 12544 + (size_t)quarter * 28 * 112;
    const int t = threadIdx.x;

    // ---- per-block redundant params: Gaussian + pad + bilinear translate ----
    if (t < 49) {
        const int p = t;
        const float inv4096 = 1.0f / 4096.0f;
        const float wsx = g_ws[p] * inv4096;
        const float wsy = g_ws[49 + p] * inv4096;
        const float wop = g_ws[98 + p] * inv4096;
        const float wrho = g_ws[147 + p] * inv4096;
        const float a = wsx * wsx + 1e-5f;
        const float dd = wsy * wsy + 1e-5f;
        const float bb = wrho * wsx * wsy;
        const float det = a * dd - bb * bb;
        const float ia = dd / det, ib = -bb / det, id = a / det;
        const float norm = 1.0f / (6.283185307179586f * sqrtf(det));

        float* kr = &kp[p * 49];
#pragma unroll
        for (int i = 0; i < 49; i++) kr[i] = 0.0f;

        float m = -1e30f;
#pragma unroll
        for (int u = 0; u < 5; u++) {
            const float x = -5.0f + 2.5f * (float)u;
#pragma unroll
            for (int v2 = 0; v2 < 5; v2++) {
                const float y = -5.0f + 2.5f * (float)v2;
                const float z = -0.5f * (ia * x * x + 2.0f * ib * x * y + id * y * y);
                const float kv = expf(z) * norm;
                m = fmaxf(m, kv);
                kr[(u + 1) * 7 + (v2 + 1)] = kv;
            }
        }
        const float invm = 1.0f / m;
#pragma unroll
        for (int u = 0; u < 5; u++)
#pragma unroll
            for (int v2 = 0; v2 < 5; v2++) kr[(u + 1) * 7 + (v2 + 1)] *= invm;

        // bilinear translate, exactly like reference
        const int rr = p / 7, cc = p % 7;
        const float tx = 1.0f - 2.0f * (float)cc / 7.0f;
        const float ty = 1.0f - 2.0f * (float)rr / 7.0f;
        const float sxp = tx * 3.0f;   // tx*(COL-1)/2
        const float syp = ty * 3.0f;   // ty*(ROW-1)/2

        for (int i = 0; i < 7; i++) {
            const float ii = (float)i + syp;
            const float i0 = floorf(ii);
            const float wi = ii - i0;
            for (int j = 0; j < 7; j++) {
                const float jj = (float)j + sxp;
                const float j0 = floorf(jj);
                const float wj = jj - j0;
                auto G = [&](float iz, float jz) -> float {
                    if (iz < 0.0f || iz > 6.0f || jz < 0.0f || jz > 6.0f) return 0.0f;
                    return kr[(int)iz * 7 + (int)jz];
                };
                const float v00 = G(i0, j0);
                const float v01 = G(i0, j0 + 1.0f);
                const float v10 = G(i0 + 1.0f, j0);
                const float v11 = G(i0 + 1.0f, j0 + 1.0f);
                const float kT = v00 * (1.0f - wi) * (1.0f - wj) + v01 * (1.0f - wi) * wj +
                                 v10 * wi * (1.0f - wj) + v11 * wi * wj;
                const float wv = wop * kT;
                sW2[p * 50 + i * 7 + j] = make_float2(wv, wv);
            }
        }
    }

    // ---- coalesced gather of 28x112 band into transposed patch layout ----
    if (t < 112) {
        const int w = t;
        const int pcol = w / 7;
        const int pc = w % 7;
#pragma unroll
        for (int h = 0; h < 28; h++) {
            const int patch = (h / 7) * 16 + pcol;     // compile-time h/7, h%7
            const int pos = (h % 7) * 7 + pc;
            sInT[pos * 66 + patch] = src[h * 112 + w];
        }
    }
    __syncthreads();

    // ---- compute: 49x49 weight apply, 2 patches per thread via f32x2 ----
    const int qq = t >> 5;            // warp id = q-quarter
    const int lane = t & 31;          // patch pair: 2*lane, 2*lane+1
    const int q0 = 12 * qq;
    const bool last = (qq == 3);

    unsigned long long acc[13];
#pragma unroll
    for (int u = 0; u < 13; u++) acc[u] = 0ull;

#pragma unroll 7
    for (int p = 0; p < 49; p++) {
        const unsigned long long xin2 =
            *(const unsigned long long*)&sInT[p * 66 + 2 * lane];
        const ulonglong2* wp = (const ulonglong2*)(sW2 + p * 50 + q0);
#pragma unroll
        for (int g = 0; g < 6; g++) {
            const ulonglong2 wv = wp[g];
            fma2(acc[2 * g + 0], xin2, wv.x);
            fma2(acc[2 * g + 1], xin2, wv.y);
        }
        if (last) {
            const unsigned long long w48 =
                *(const unsigned long long*)(sW2 + p * 50 + 48);
            fma2(acc[12], xin2, w48);
        }
    }
    __syncthreads();   // all reads of sInT done before overwrite

    // ---- writeback: packed pair store straight into transposed layout ----
#pragma unroll
    for (int u = 0; u < 12; u++)
        *(unsigned long long*)&sInT[(q0 + u) * 66 + 2 * lane] = acc[u];
    if (last) *(unsigned long long*)&sInT[48 * 66 + 2 * lane] = acc[12];
    __syncthreads();

    // ---- coalesced store ----
    if (t < 112) {
        const int w = t;
        const int pcol = w / 7;
        const int pc = w % 7;
#pragma unroll
        for (int h = 0; h < 28; h++) {
            const int patch = (h / 7) * 16 + pcol;
            const int pos = (h % 7) * 7 + pc;
            dst[h * 112 + w] = sInT[pos * 66 + patch];
        }
    }
}

// ---------------- launcher ----------------
extern "C" void kernel_launch(void* const* d_in, const int* in_sizes, int n_in,
                              void* d_out, int out_size) {
    const float* inp    = (const float*)d_in[0];  // (16,64,112,112)
    const float* logits = (const float*)d_in[1];  // (16,100,112,112)
    const float* sigx   = (const float*)d_in[2];  // (100)
    const float* sigy   = (const float*)d_in[3];  // (100)
    const float* opac   = (const float*)d_in[4];  // (100,1) flat
    const float* rho    = (const float*)d_in[5];  // (100,1) flat
    float* out = (float*)d_out;                   // (16,8,112,112)

    k_zero<<<1, 256>>>();
    k_reduce<<<1600, 224>>>(logits, sigx, sigy, opac, rho);
    k_apply<<<512, 128>>>(inp, out);
}

// round 4
// speedup vs baseline: 1.0736x; 1.0736x over previous
#include <cuda_runtime.h>
#include <math.h>

// ---------------- scratch (no allocations allowed) ----------------
__device__ float g_partial[49 * 1600];   // [p][plane] per-plane phase sums
__device__ float2 g_W2[49 * 50];         // W[p][q] duplicated pairs, rows padded to 50

// ---------------- packed f32x2 FMA helper (sm_103a FFMA2) ----------------
__device__ __forceinline__ void fma2(unsigned long long& acc, unsigned long long xy,
                                     unsigned long long w) {
    asm("fma.rn.f32x2 %0, %1, %2, %0;" : "+l"(acc) : "l"(xy), "l"(w));
}

// ---------------- kernel 1: logits -> per-plane 49 phase sums ----------------
// grid = 1600 (one plane b*100+n per block), block = 224 threads.
__global__ void __launch_bounds__(224) k_reduce(const float* __restrict__ logits) {
    const int plane = blockIdx.x;                 // b*100 + n
    const float4* __restrict__ base4 =
        (const float4*)(logits + (size_t)plane * 12544);
    const int t = threadIdx.x;
    const int c4 = t % 28;
    const int rb = t / 28;

    __shared__ float s[224 * 29];   // [t][28] padded to 29 (conflict-free)
    __shared__ float s2[784];       // [c4][28]

    float acc[7][4];
#pragma unroll
    for (int i = 0; i < 7; i++)
#pragma unroll
        for (int j = 0; j < 4; j++) acc[i][j] = 0.0f;

#pragma unroll
    for (int k = 0; k < 14; k++) {
        const int r = rb * 14 + k;
        const float4 v = __ldcs(&base4[r * 28 + c4]);   // read-once streaming
        const int ph = k % 7;
        acc[ph][0] += v.x;
        acc[ph][1] += v.y;
        acc[ph][2] += v.z;
        acc[ph][3] += v.w;
    }

#pragma unroll
    for (int ph = 0; ph < 7; ph++)
#pragma unroll
        for (int j = 0; j < 4; j++) s[t * 29 + ph * 4 + j] = acc[ph][j];
    __syncthreads();

    // reduce over the 8 row-bands: s2[c4*28 + i] = sum_rb s[(rb*28+c4)*29 + i]
#pragma unroll
    for (int u = 0; u < 4; u++) {
        const int id = u * 224 + t;
        if (id < 784) {
            const int cc4 = id / 28;
            const int i = id % 28;
            float sum = 0.0f;
#pragma unroll
            for (int r8 = 0; r8 < 8; r8++) sum += s[(r8 * 28 + cc4) * 29 + i];
            s2[cc4 * 28 + i] = sum;
        }
    }
    __syncthreads();

    // fold column groups into the 49 (row-phase, col-phase) bins; plain store
    if (t < 49) {
        const int rp = t / 7, cp = t % 7;
        float sum = 0.0f;
#pragma unroll
        for (int cc4 = 0; cc4 < 28; cc4++) {
            const int j = (cp + 112 - 4 * cc4) % 7;  // which of the 4 lanes maps to cp
            if (j < 4) sum += s2[cc4 * 28 + rp * 4 + j];
        }
        g_partial[t * 1600 + plane] = sum;
    }
}

// ---------------- kernel 2: per-p weighted reduce + Gaussian + translate ----------------
// grid = 49 (one block per patch position p), block = 256 threads.
__global__ void __launch_bounds__(256) k_params(const float* __restrict__ sigx,
                                                const float* __restrict__ sigy,
                                                const float* __restrict__ opac,
                                                const float* __restrict__ rho) {
    const int p = blockIdx.x;
    const int t = threadIdx.x;

    __shared__ float sv[400];       // [sigx|sigy|op|rho]
    __shared__ float red[8][4];
    __shared__ float kr[49];

    if (t < 100) {
        sv[t] = sigx[t];
        sv[100 + t] = sigy[t];
        sv[200 + t] = opac[t];
        sv[300 + t] = rho[t];
    }
    __syncthreads();

    float a0 = 0.0f, a1 = 0.0f, a2 = 0.0f, a3 = 0.0f;
    const float* row = &g_partial[p * 1600];
    for (int plane = t; plane < 1600; plane += 256) {
        const float s = row[plane];
        const int n = plane % 100;
        a0 += s * sv[n];
        a1 += s * sv[100 + n];
        a2 += s * sv[200 + n];
        a3 += s * sv[300 + n];
    }
#pragma unroll
    for (int off = 16; off > 0; off >>= 1) {
        a0 += __shfl_down_sync(0xffffffffu, a0, off);
        a1 += __shfl_down_sync(0xffffffffu, a1, off);
        a2 += __shfl_down_sync(0xffffffffu, a2, off);
        a3 += __shfl_down_sync(0xffffffffu, a3, off);
    }
    if ((t & 31) == 0) {
        red[t >> 5][0] = a0;
        red[t >> 5][1] = a1;
        red[t >> 5][2] = a2;
        red[t >> 5][3] = a3;
    }
    __syncthreads();

    if (t == 0) {
        float w0 = 0.0f, w1 = 0.0f, w2 = 0.0f, w3 = 0.0f;
#pragma unroll
        for (int i = 0; i < 8; i++) {
            w0 += red[i][0];
            w1 += red[i][1];
            w2 += red[i][2];
            w3 += red[i][3];
        }
        const float inv4096 = 1.0f / 4096.0f;
        const float wsx = w0 * inv4096, wsy = w1 * inv4096;
        const float wop = w2 * inv4096, wrho = w3 * inv4096;
        const float a = wsx * wsx + 1e-5f;
        const float dd = wsy * wsy + 1e-5f;
        const float bb = wrho * wsx * wsy;
        const float det = a * dd - bb * bb;
        const float ia = dd / det, ib = -bb / det, id = a / det;
        const float norm = 1.0f / (6.283185307179586f * sqrtf(det));

#pragma unroll
        for (int i = 0; i < 49; i++) kr[i] = 0.0f;

        float m = -1e30f;
#pragma unroll
        for (int u = 0; u < 5; u++) {
            const float x = -5.0f + 2.5f * (float)u;
#pragma unroll
            for (int v2 = 0; v2 < 5; v2++) {
                const float y = -5.0f + 2.5f * (float)v2;
                const float z = -0.5f * (ia * x * x + 2.0f * ib * x * y + id * y * y);
                const float kv = expf(z) * norm;
                m = fmaxf(m, kv);
                kr[(u + 1) * 7 + (v2 + 1)] = kv;
            }
        }
        const float invm = 1.0f / m;
#pragma unroll
        for (int u = 0; u < 5; u++)
#pragma unroll
            for (int v2 = 0; v2 < 5; v2++) kr[(u + 1) * 7 + (v2 + 1)] *= invm;

        // bilinear translate, exactly like reference
        const int rr = p / 7, cc = p % 7;
        const float tx = 1.0f - 2.0f * (float)cc / 7.0f;
        const float ty = 1.0f - 2.0f * (float)rr / 7.0f;
        const float sxp = tx * 3.0f;   // tx*(COL-1)/2
        const float syp = ty * 3.0f;   // ty*(ROW-1)/2

        for (int i = 0; i < 7; i++) {
            const float ii = (float)i + syp;
            const float i0 = floorf(ii);
            const float wi = ii - i0;
            for (int j = 0; j < 7; j++) {
                const float jj = (float)j + sxp;
                const float j0 = floorf(jj);
                const float wj = jj - j0;
                auto G = [&](float iz, float jz) -> float {
                    if (iz < 0.0f || iz > 6.0f || jz < 0.0f || jz > 6.0f) return 0.0f;
                    return kr[(int)iz * 7 + (int)jz];
                };
                const float v00 = G(i0, j0);
                const float v01 = G(i0, j0 + 1.0f);
                const float v10 = G(i0 + 1.0f, j0);
                const float v11 = G(i0 + 1.0f, j0 + 1.0f);
                const float kT = v00 * (1.0f - wi) * (1.0f - wj) + v01 * (1.0f - wi) * wj +
                                 v10 * wi * (1.0f - wj) + v11 * wi * wj;
                const float wv = wop * kT;
                g_W2[p * 50 + i * 7 + j] = make_float2(wv, wv);
            }
        }
    }
}

// ---------------- kernel 3: splat-apply (49x49 per patch, f32x2) ----------------
// grid = 512 (bc=128 x quarter-bands of 28 rows), block = 128 threads.
__global__ void __launch_bounds__(128) k_apply(const float* __restrict__ inp,
                                               float* __restrict__ out) {
    __shared__ __align__(16) float sInT[49 * 66];       // [p][patch], stride 66
    __shared__ __align__(16) float2 sW2[49 * 50];       // W[p][q] duplicated pairs

    const int blk = blockIdx.x;
    const int bc = blk >> 2;          // b*8 + c
    const int quarter = blk & 3;
    const int b = bc >> 3, c = bc & 7;
    const float* src = inp + ((size_t)b * 64 + c) * 12544 + (size_t)quarter * 28 * 112;
    float* dst = out + (size_t)bc * 12544 + (size_t)quarter * 28 * 112;
    const int t = threadIdx.x;

    // load fused weights
    for (int i = t; i < 49 * 50; i += 128) sW2[i] = g_W2[i];

    // coalesced gather of 28x112 band into transposed patch layout
    if (t < 112) {
        const int w = t;
        const int pcol = w / 7;
        const int pc = w % 7;
#pragma unroll
        for (int h = 0; h < 28; h++) {
            const int patch = (h / 7) * 16 + pcol;     // compile-time h/7, h%7
            const int pos = (h % 7) * 7 + pc;
            sInT[pos * 66 + patch] = __ldcs(&src[h * 112 + w]);
        }
    }
    __syncthreads();

    // compute: warp = q-quarter, lane = patch-pair -> patches 2*lane, 2*lane+1
    const int qq = t >> 5;
    const int lane = t & 31;
    const int q0 = 12 * qq;
    const bool last = (qq == 3);

    unsigned long long acc[13];
#pragma unroll
    for (int u = 0; u < 13; u++) acc[u] = 0ull;

#pragma unroll 7
    for (int p = 0; p < 49; p++) {
        const unsigned long long xin2 =
            *(const unsigned long long*)&sInT[p * 66 + 2 * lane];
        const ulonglong2* wp = (const ulonglong2*)(sW2 + p * 50 + q0);
#pragma unroll
        for (int g = 0; g < 6; g++) {
            const ulonglong2 wv = wp[g];
            fma2(acc[2 * g + 0], xin2, wv.x);
            fma2(acc[2 * g + 1], xin2, wv.y);
        }
        if (last) {
            const unsigned long long w48 =
                *(const unsigned long long*)(sW2 + p * 50 + 48);
            fma2(acc[12], xin2, w48);
        }
    }
    __syncthreads();   // all reads of sInT done before overwrite

    // writeback into transposed layout (disjoint q ranges per warp)
#pragma unroll
    for (int u = 0; u < 12; u++)
        *(unsigned long long*)&sInT[(q0 + u) * 66 + 2 * lane] = acc[u];
    if (last) *(unsigned long long*)&sInT[48 * 66 + 2 * lane] = acc[12];
    __syncthreads();

    // coalesced store
    if (t < 112) {
        const int w = t;
        const int pcol = w / 7;
        const int pc = w % 7;
#pragma unroll
        for (int h = 0; h < 28; h++) {
            const int patch = (h / 7) * 16 + pcol;
            const int pos = (h % 7) * 7 + pc;
            dst[h * 112 + w] = sInT[pos * 66 + patch];
        }
    }
}

// ---------------- launcher ----------------
extern "C" void kernel_launch(void* const* d_in, const int* in_sizes, int n_in,
                              void* d_out, int out_size) {
    const float* inp    = (const float*)d_in[0];  // (16,64,112,112)
    const float* logits = (const float*)d_in[1];  // (16,100,112,112)
    const float* sigx   = (const float*)d_in[2];  // (100)
    const float* sigy   = (const float*)d_in[3];  // (100)
    const float* opac   = (const float*)d_in[4];  // (100,1) flat
    const float* rho    = (const float*)d_in[5];  // (100,1) flat
    float* out = (float*)d_out;                   // (16,8,112,112)

    k_reduce<<<1600, 224>>>(logits);
    k_params<<<49, 256>>>(sigx, sigy, opac, rho);
    k_apply<<<512, 128>>>(inp, out);
}

// round 5
// speedup vs baseline: 1.3481x; 1.2557x over previous
#include <cuda_runtime.h>
#include <math.h>

// ---------------- scratch (no allocations allowed) ----------------
__device__ float g_partial[49 * 3200];   // [p][blk] per-halfplane phase sums
__device__ float2 g_W2[49 * 50];         // W[p][q] duplicated pairs, rows padded to 50

// ---------------- packed f32x2 FMA helper (sm_103a FFMA2) ----------------
__device__ __forceinline__ void fma2(unsigned long long& acc, unsigned long long xy,
                                     unsigned long long w) {
    asm("fma.rn.f32x2 %0, %1, %2, %0;" : "+l"(acc) : "l"(xy), "l"(w));
}

// ---------------- kernel 1: logits -> per-halfplane 49 phase sums ----------------
// grid = 3200 (plane*2 + half), block = 196 threads = 28 col-groups x 7 row-phases.
// Each thread: 8 batched independent LDG.128 of rows sharing one row-phase.
__global__ void __launch_bounds__(196) k_reduce(const float* __restrict__ logits) {
    const int blk = blockIdx.x;
    const float4* __restrict__ base4 =
        (const float4*)logits + (size_t)(blk >> 1) * 3136 + (size_t)(blk & 1) * 1568;
    const int t = threadIdx.x;
    const int c4 = t % 28;   // float4 column group
    const int ph = t / 28;   // row phase 0..6

    __shared__ float4 s2[196];   // [ph*28 + c4]

    float4 v[8];
#pragma unroll
    for (int k = 0; k < 8; k++)
        v[k] = __ldcs(&base4[(ph + 7 * k) * 28 + c4]);   // MLP=8, all independent

    float4 a;
    a.x = ((v[0].x + v[1].x) + (v[2].x + v[3].x)) + ((v[4].x + v[5].x) + (v[6].x + v[7].x));
    a.y = ((v[0].y + v[1].y) + (v[2].y + v[3].y)) + ((v[4].y + v[5].y) + (v[6].y + v[7].y));
    a.z = ((v[0].z + v[1].z) + (v[2].z + v[3].z)) + ((v[4].z + v[5].z) + (v[6].z + v[7].z));
    a.w = ((v[0].w + v[1].w) + (v[2].w + v[3].w)) + ((v[4].w + v[5].w) + (v[6].w + v[7].w));
    s2[ph * 28 + c4] = a;
    __syncthreads();

    // fold column lanes into the 49 (row-phase, col-phase) bins
    if (t < 49) {
        const int rp = t / 7, cp = t % 7;
        const float* s2f = (const float*)s2;
        float sum = 0.0f;
#pragma unroll
        for (int c = 0; c < 28; c++) {
            const int j = (cp + 112 - 4 * c) % 7;   // lane with (4c+j)%7 == cp
            if (j < 4) sum += s2f[(rp * 28 + c) * 4 + j];
        }
        g_partial[t * 3200 + blk] = sum;
    }
}

// ---------------- kernel 2: per-p weighted reduce + Gaussian + translate ----------------
// grid = 49 (one block per patch position p), block = 256 threads.
__global__ void __launch_bounds__(256) k_params(const float* __restrict__ sigx,
                                                const float* __restrict__ sigy,
                                                const float* __restrict__ opac,
                                                const float* __restrict__ rho) {
    const int p = blockIdx.x;
    const int t = threadIdx.x;

    __shared__ float sv[400];       // [sigx|sigy|op|rho]
    __shared__ float red[8][4];
    __shared__ float kr[49];

    if (t < 100) {
        sv[t] = sigx[t];
        sv[100 + t] = sigy[t];
        sv[200 + t] = opac[t];
        sv[300 + t] = rho[t];
    }
    __syncthreads();

    const float* row = &g_partial[p * 3200];
    float buf[13];
#pragma unroll
    for (int i = 0; i < 13; i++) {
        const int idx = t + i * 256;
        buf[i] = (idx < 3200) ? row[idx] : 0.0f;   // batched, MLP=13
    }
    float a0 = 0.0f, a1 = 0.0f, a2 = 0.0f, a3 = 0.0f;
#pragma unroll
    for (int i = 0; i < 13; i++) {
        const int idx = t + i * 256;
        if (idx < 3200) {
            const int n = (idx >> 1) % 100;
            a0 += buf[i] * sv[n];
            a1 += buf[i] * sv[100 + n];
            a2 += buf[i] * sv[200 + n];
            a3 += buf[i] * sv[300 + n];
        }
    }
#pragma unroll
    for (int off = 16; off > 0; off >>= 1) {
        a0 += __shfl_down_sync(0xffffffffu, a0, off);
        a1 += __shfl_down_sync(0xffffffffu, a1, off);
        a2 += __shfl_down_sync(0xffffffffu, a2, off);
        a3 += __shfl_down_sync(0xffffffffu, a3, off);
    }
    if ((t & 31) == 0) {
        red[t >> 5][0] = a0;
        red[t >> 5][1] = a1;
        red[t >> 5][2] = a2;
        red[t >> 5][3] = a3;
    }
    __syncthreads();

    if (t == 0) {
        float w0 = 0.0f, w1 = 0.0f, w2 = 0.0f, w3 = 0.0f;
#pragma unroll
        for (int i = 0; i < 8; i++) {
            w0 += red[i][0];
            w1 += red[i][1];
            w2 += red[i][2];
            w3 += red[i][3];
        }
        const float inv4096 = 1.0f / 4096.0f;
        const float wsx = w0 * inv4096, wsy = w1 * inv4096;
        const float wop = w2 * inv4096, wrho = w3 * inv4096;
        const float a = wsx * wsx + 1e-5f;
        const float dd = wsy * wsy + 1e-5f;
        const float bb = wrho * wsx * wsy;
        const float det = a * dd - bb * bb;
        const float ia = dd / det, ib = -bb / det, id = a / det;
        const float norm = 1.0f / (6.283185307179586f * sqrtf(det));

#pragma unroll
        for (int i = 0; i < 49; i++) kr[i] = 0.0f;

        float m = -1e30f;
#pragma unroll
        for (int u = 0; u < 5; u++) {
            const float x = -5.0f + 2.5f * (float)u;
#pragma unroll
            for (int v2 = 0; v2 < 5; v2++) {
                const float y = -5.0f + 2.5f * (float)v2;
                const float z = -0.5f * (ia * x * x + 2.0f * ib * x * y + id * y * y);
                const float kv = expf(z) * norm;
                m = fmaxf(m, kv);
                kr[(u + 1) * 7 + (v2 + 1)] = kv;
            }
        }
        const float invm = 1.0f / m;
#pragma unroll
        for (int u = 0; u < 5; u++)
#pragma unroll
            for (int v2 = 0; v2 < 5; v2++) kr[(u + 1) * 7 + (v2 + 1)] *= invm;

        // bilinear translate, exactly like reference
        const int rr = p / 7, cc = p % 7;
        const float tx = 1.0f - 2.0f * (float)cc / 7.0f;
        const float ty = 1.0f - 2.0f * (float)rr / 7.0f;
        const float sxp = tx * 3.0f;
        const float syp = ty * 3.0f;

        for (int i = 0; i < 7; i++) {
            const float ii = (float)i + syp;
            const float i0 = floorf(ii);
            const float wi = ii - i0;
            for (int j = 0; j < 7; j++) {
                const float jj = (float)j + sxp;
                const float j0 = floorf(jj);
                const float wj = jj - j0;
                auto G = [&](float iz, float jz) -> float {
                    if (iz < 0.0f || iz > 6.0f || jz < 0.0f || jz > 6.0f) return 0.0f;
                    return kr[(int)iz * 7 + (int)jz];
                };
                const float v00 = G(i0, j0);
                const float v01 = G(i0, j0 + 1.0f);
                const float v10 = G(i0 + 1.0f, j0);
                const float v11 = G(i0 + 1.0f, j0 + 1.0f);
                const float kT = v00 * (1.0f - wi) * (1.0f - wj) + v01 * (1.0f - wi) * wj +
                                 v10 * wi * (1.0f - wj) + v11 * wi * wj;
                const float wv = wop * kT;
                g_W2[p * 50 + i * 7 + j] = make_float2(wv, wv);
            }
        }
    }
}

// ---------------- kernel 3: splat-apply (49x49 per patch, f32x2) ----------------
// grid = 256 (bc=128 x half-bands of 56 rows), block = 256 threads (8 warps).
__global__ void __launch_bounds__(256) k_apply(const float* __restrict__ inp,
                                               float* __restrict__ out) {
    __shared__ __align__(16) float sInT[49 * 130];      // [pos][patch], 128 patches, stride 130
    __shared__ __align__(16) float2 sW2[49 * 50];       // W[p][q] duplicated pairs

    const int blk = blockIdx.x;
    const int bc = blk >> 1;          // b*8 + c
    const int half = blk & 1;
    const int b = bc >> 3, c = bc & 7;
    const float* src = inp + ((size_t)b * 64 + c) * 12544 + (size_t)half * 56 * 112;
    float* dst = out + (size_t)bc * 12544 + (size_t)half * 56 * 112;
    const int t = threadIdx.x;

    // fused-weight load (batched)
    {
        float2 wb[10];
#pragma unroll
        for (int i = 0; i < 10; i++) {
            const int idx = t + i * 256;
            wb[i] = (idx < 2450) ? g_W2[idx] : make_float2(0.0f, 0.0f);
        }
#pragma unroll
        for (int i = 0; i < 10; i++) {
            const int idx = t + i * 256;
            if (idx < 2450) sW2[idx] = wb[i];
        }
    }

    // coalesced gather of 56x112 band into transposed patch layout (batched loads)
    if (t < 224) {
        const int w = t % 112;
        const int hh = t / 112;        // 0/1: rows hh*28 .. hh*28+27
        const int pcol = w / 7, pc = w % 7;
        float buf[14];
#pragma unroll
        for (int k = 0; k < 14; k++)
            buf[k] = __ldcs(&src[(hh * 28 + k) * 112 + w]);
#pragma unroll
        for (int k = 0; k < 14; k++) {
            const int prow = hh * 4 + k / 7;
            const int pos = (k % 7) * 7 + pc;
            sInT[pos * 130 + prow * 16 + pcol] = buf[k];
        }
#pragma unroll
        for (int k = 0; k < 14; k++)
            buf[k] = __ldcs(&src[(hh * 28 + 14 + k) * 112 + w]);
#pragma unroll
        for (int k = 0; k < 14; k++) {
            const int kk = 14 + k;
            const int prow = hh * 4 + kk / 7;
            const int pos = (kk % 7) * 7 + pc;
            sInT[pos * 130 + prow * 16 + pcol] = buf[k];
        }
    }
    __syncthreads();

    // compute: warp -> (q-quarter, patch-pair half); thread handles 2 patches via f32x2
    const int wid = t >> 5;
    const int lane = t & 31;
    const int qq = wid & 3;
    const int phalf = wid >> 2;
    const int pair = phalf * 32 + lane;   // 0..63 -> patches 2*pair, 2*pair+1
    const int q0 = 12 * qq;
    const bool lastq = (qq == 3);

    unsigned long long acc[13];
#pragma unroll
    for (int u = 0; u < 13; u++) acc[u] = 0ull;

#pragma unroll 7
    for (int p = 0; p < 49; p++) {
        const unsigned long long xin2 =
            *(const unsigned long long*)&sInT[p * 130 + 2 * pair];
        const ulonglong2* wp = (const ulonglong2*)(sW2 + p * 50 + q0);
#pragma unroll
        for (int g = 0; g < 6; g++) {
            const ulonglong2 wv = wp[g];
            fma2(acc[2 * g + 0], xin2, wv.x);
            fma2(acc[2 * g + 1], xin2, wv.y);
        }
        if (lastq) {
            const unsigned long long w48 =
                *(const unsigned long long*)(sW2 + p * 50 + 48);
            fma2(acc[12], xin2, w48);
        }
    }
    __syncthreads();   // all reads of sInT done before overwrite

    // writeback into transposed layout (disjoint (q, pair) ranges per warp)
#pragma unroll
    for (int u = 0; u < 12; u++)
        *(unsigned long long*)&sInT[(q0 + u) * 130 + 2 * pair] = acc[u];
    if (lastq) *(unsigned long long*)&sInT[48 * 130 + 2 * pair] = acc[12];
    __syncthreads();

    // coalesced store
    if (t < 224) {
        const int w = t % 112;
        const int hh = t / 112;
        const int pcol = w / 7, pc = w % 7;
#pragma unroll
        for (int k = 0; k < 28; k++) {
            const int prow = hh * 4 + k / 7;
            const int pos = (k % 7) * 7 + pc;
            dst[(hh * 28 + k) * 112 + w] = sInT[pos * 130 + prow * 16 + pcol];
        }
    }
}

// ---------------- launcher ----------------
extern "C" void kernel_launch(void* const* d_in, const int* in_sizes, int n_in,
                              void* d_out, int out_size) {
    const float* inp    = (const float*)d_in[0];  // (16,64,112,112)
    const float* logits = (const float*)d_in[1];  // (16,100,112,112)
    const float* sigx   = (const float*)d_in[2];  // (100)
    const float* sigy   = (const float*)d_in[3];  // (100)
    const float* opac   = (const float*)d_in[4];  // (100,1) flat
    const float* rho    = (const float*)d_in[5];  // (100,1) flat
    float* out = (float*)d_out;                   // (16,8,112,112)

    k_reduce<<<3200, 196>>>(logits);
    k_params<<<49, 256>>>(sigx, sigy, opac, rho);
    k_apply<<<256, 256>>>(inp, out);
}

// round 6
// speedup vs baseline: 1.4312x; 1.0616x over previous
#include <cuda_runtime.h>
#include <math.h>

// ---------------- scratch (no allocations allowed) ----------------
__device__ float g_partial[49 * 3200];   // [p][blk] per-halfplane phase sums
__device__ float2 g_W2[49 * 50];         // W[p][q] duplicated pairs, rows padded to 50

// ---------------- packed f32x2 FMA helper (sm_103a FFMA2) ----------------
__device__ __forceinline__ void fma2(unsigned long long& acc, unsigned long long xy,
                                     unsigned long long w) {
    asm("fma.rn.f32x2 %0, %1, %2, %0;" : "+l"(acc) : "l"(xy), "l"(w));
}

// ---------------- kernel 1: logits -> per-halfplane 49 phase sums ----------------
// grid = 3200 (plane*2 + half), block = 196 threads = 28 col-groups x 7 row-phases.
// Each thread: 8 batched independent LDG.128 of rows sharing one row-phase.
__global__ void __launch_bounds__(196) k_reduce(const float* __restrict__ logits) {
    const int blk = blockIdx.x;
    const float4* __restrict__ base4 =
        (const float4*)logits + (size_t)(blk >> 1) * 3136 + (size_t)(blk & 1) * 1568;
    const int t = threadIdx.x;
    const int c4 = t % 28;   // float4 column group
    const int ph = t / 28;   // row phase 0..6

    __shared__ float4 s2[196];   // [ph*28 + c4]

    float4 v[8];
#pragma unroll
    for (int k = 0; k < 8; k++)
        v[k] = __ldcs(&base4[(ph + 7 * k) * 28 + c4]);   // MLP=8, all independent

    float4 a;
    a.x = ((v[0].x + v[1].x) + (v[2].x + v[3].x)) + ((v[4].x + v[5].x) + (v[6].x + v[7].x));
    a.y = ((v[0].y + v[1].y) + (v[2].y + v[3].y)) + ((v[4].y + v[5].y) + (v[6].y + v[7].y));
    a.z = ((v[0].z + v[1].z) + (v[2].z + v[3].z)) + ((v[4].z + v[5].z) + (v[6].z + v[7].z));
    a.w = ((v[0].w + v[1].w) + (v[2].w + v[3].w)) + ((v[4].w + v[5].w) + (v[6].w + v[7].w));
    s2[ph * 28 + c4] = a;
    __syncthreads();

    // fold column lanes into the 49 (row-phase, col-phase) bins
    if (t < 49) {
        const int rp = t / 7, cp = t % 7;
        const float* s2f = (const float*)s2;
        float sum = 0.0f;
#pragma unroll
        for (int c = 0; c < 28; c++) {
            const int j = (cp + 112 - 4 * c) % 7;   // lane with (4c+j)%7 == cp
            if (j < 4) sum += s2f[(rp * 28 + c) * 4 + j];
        }
        g_partial[t * 3200 + blk] = sum;
    }
}

// ---------------- kernel 2: per-p weighted reduce + Gaussian + translate ----------------
// grid = 49 (one block per patch position p), block = 256 threads.
__global__ void __launch_bounds__(256) k_params(const float* __restrict__ sigx,
                                                const float* __restrict__ sigy,
                                                const float* __restrict__ opac,
                                                const float* __restrict__ rho) {
    const int p = blockIdx.x;
    const int t = threadIdx.x;

    __shared__ float sv[400];       // [sigx|sigy|op|rho]
    __shared__ float red[8][4];
    __shared__ float kr[49];

    if (t < 100) {
        sv[t] = sigx[t];
        sv[100 + t] = sigy[t];
        sv[200 + t] = opac[t];
        sv[300 + t] = rho[t];
    }
    __syncthreads();

    const float* row = &g_partial[p * 3200];
    float buf[13];
#pragma unroll
    for (int i = 0; i < 13; i++) {
        const int idx = t + i * 256;
        buf[i] = (idx < 3200) ? row[idx] : 0.0f;   // batched, MLP=13
    }
    float a0 = 0.0f, a1 = 0.0f, a2 = 0.0f, a3 = 0.0f;
#pragma unroll
    for (int i = 0; i < 13; i++) {
        const int idx = t + i * 256;
        if (idx < 3200) {
            const int n = (idx >> 1) % 100;
            a0 += buf[i] * sv[n];
            a1 += buf[i] * sv[100 + n];
            a2 += buf[i] * sv[200 + n];
            a3 += buf[i] * sv[300 + n];
        }
    }
#pragma unroll
    for (int off = 16; off > 0; off >>= 1) {
        a0 += __shfl_down_sync(0xffffffffu, a0, off);
        a1 += __shfl_down_sync(0xffffffffu, a1, off);
        a2 += __shfl_down_sync(0xffffffffu, a2, off);
        a3 += __shfl_down_sync(0xffffffffu, a3, off);
    }
    if ((t & 31) == 0) {
        red[t >> 5][0] = a0;
        red[t >> 5][1] = a1;
        red[t >> 5][2] = a2;
        red[t >> 5][3] = a3;
    }
    __syncthreads();

    if (t == 0) {
        float w0 = 0.0f, w1 = 0.0f, w2 = 0.0f, w3 = 0.0f;
#pragma unroll
        for (int i = 0; i < 8; i++) {
            w0 += red[i][0];
            w1 += red[i][1];
            w2 += red[i][2];
            w3 += red[i][3];
        }
        const float inv4096 = 1.0f / 4096.0f;
        const float wsx = w0 * inv4096, wsy = w1 * inv4096;
        const float wop = w2 * inv4096, wrho = w3 * inv4096;
        const float a = wsx * wsx + 1e-5f;
        const float dd = wsy * wsy + 1e-5f;
        const float bb = wrho * wsx * wsy;
        const float det = a * dd - bb * bb;
        const float ia = dd / det, ib = -bb / det, id = a / det;
        const float norm = 1.0f / (6.283185307179586f * sqrtf(det));

#pragma unroll
        for (int i = 0; i < 49; i++) kr[i] = 0.0f;

        float m = -1e30f;
#pragma unroll
        for (int u = 0; u < 5; u++) {
            const float x = -5.0f + 2.5f * (float)u;
#pragma unroll
            for (int v2 = 0; v2 < 5; v2++) {
                const float y = -5.0f + 2.5f * (float)v2;
                const float z = -0.5f * (ia * x * x + 2.0f * ib * x * y + id * y * y);
                const float kv = expf(z) * norm;
                m = fmaxf(m, kv);
                kr[(u + 1) * 7 + (v2 + 1)] = kv;
            }
        }
        const float invm = 1.0f / m;
#pragma unroll
        for (int u = 0; u < 5; u++)
#pragma unroll
            for (int v2 = 0; v2 < 5; v2++) kr[(u + 1) * 7 + (v2 + 1)] *= invm;

        // bilinear translate, exactly like reference
        const int rr = p / 7, cc = p % 7;
        const float tx = 1.0f - 2.0f * (float)cc / 7.0f;
        const float ty = 1.0f - 2.0f * (float)rr / 7.0f;
        const float sxp = tx * 3.0f;
        const float syp = ty * 3.0f;

        for (int i = 0; i < 7; i++) {
            const float ii = (float)i + syp;
            const float i0 = floorf(ii);
            const float wi = ii - i0;
            for (int j = 0; j < 7; j++) {
                const float jj = (float)j + sxp;
                const float j0 = floorf(jj);
                const float wj = jj - j0;
                auto G = [&](float iz, float jz) -> float {
                    if (iz < 0.0f || iz > 6.0f || jz < 0.0f || jz > 6.0f) return 0.0f;
                    return kr[(int)iz * 7 + (int)jz];
                };
                const float v00 = G(i0, j0);
                const float v01 = G(i0, j0 + 1.0f);
                const float v10 = G(i0 + 1.0f, j0);
                const float v11 = G(i0 + 1.0f, j0 + 1.0f);
                const float kT = v00 * (1.0f - wi) * (1.0f - wj) + v01 * (1.0f - wi) * wj +
                                 v10 * wi * (1.0f - wj) + v11 * wi * wj;
                const float wv = wop * kT;
                g_W2[p * 50 + i * 7 + j] = make_float2(wv, wv);
            }
        }
    }
}

// ---------------- kernel 3: splat-apply (49x49 per patch, f32x2) ----------------
// grid = 256 (bc=128 x half-bands of 56 rows), block = 256 threads (8 warps).
__global__ void __launch_bounds__(256) k_apply(const float* __restrict__ inp,
                                               float* __restrict__ out) {
    __shared__ __align__(16) float sInT[49 * 130];      // [pos][patch], 128 patches, stride 130
    __shared__ __align__(16) float2 sW2[49 * 50];       // W[p][q] duplicated pairs

    const int blk = blockIdx.x;
    const int bc = blk >> 1;          // b*8 + c
    const int half = blk & 1;
    const int b = bc >> 3, c = bc & 7;
    const float* src = inp + ((size_t)b * 64 + c) * 12544 + (size_t)half * 56 * 112;
    float* dst = out + (size_t)bc * 12544 + (size_t)half * 56 * 112;
    const int t = threadIdx.x;

    // fused-weight load (batched)
    {
        float2 wb[10];
#pragma unroll
        for (int i = 0; i < 10; i++) {
            const int idx = t + i * 256;
            wb[i] = (idx < 2450) ? g_W2[idx] : make_float2(0.0f, 0.0f);
        }
#pragma unroll
        for (int i = 0; i < 10; i++) {
            const int idx = t + i * 256;
            if (idx < 2450) sW2[idx] = wb[i];
        }
    }

    // coalesced gather of 56x112 band into transposed patch layout (batched loads)
    if (t < 224) {
        const int w = t % 112;
        const int hh = t / 112;        // 0/1: rows hh*28 .. hh*28+27
        const int pcol = w / 7, pc = w % 7;
        float buf[14];
#pragma unroll
        for (int k = 0; k < 14; k++)
            buf[k] = __ldcs(&src[(hh * 28 + k) * 112 + w]);
#pragma unroll
        for (int k = 0; k < 14; k++) {
            const int prow = hh * 4 + k / 7;
            const int pos = (k % 7) * 7 + pc;
            sInT[pos * 130 + prow * 16 + pcol] = buf[k];
        }
#pragma unroll
        for (int k = 0; k < 14; k++)
            buf[k] = __ldcs(&src[(hh * 28 + 14 + k) * 112 + w]);
#pragma unroll
        for (int k = 0; k < 14; k++) {
            const int kk = 14 + k;
            const int prow = hh * 4 + kk / 7;
            const int pos = (kk % 7) * 7 + pc;
            sInT[pos * 130 + prow * 16 + pcol] = buf[k];
        }
    }
    __syncthreads();

    // compute: warp -> (q-quarter, patch-pair half); thread handles 2 patches via f32x2
    const int wid = t >> 5;
    const int lane = t & 31;
    const int qq = wid & 3;
    const int phalf = wid >> 2;
    const int pair = phalf * 32 + lane;   // 0..63 -> patches 2*pair, 2*pair+1
    const int q0 = 12 * qq;
    const bool lastq = (qq == 3);

    unsigned long long acc[13];
#pragma unroll
    for (int u = 0; u < 13; u++) acc[u] = 0ull;

#pragma unroll 7
    for (int p = 0; p < 49; p++) {
        const unsigned long long xin2 =
            *(const unsigned long long*)&sInT[p * 130 + 2 * pair];
        const ulonglong2* wp = (const ulonglong2*)(sW2 + p * 50 + q0);
#pragma unroll
        for (int g = 0; g < 6; g++) {
            const ulonglong2 wv = wp[g];
            fma2(acc[2 * g + 0], xin2, wv.x);
            fma2(acc[2 * g + 1], xin2, wv.y);
        }
        if (lastq) {
            const unsigned long long w48 =
                *(const unsigned long long*)(sW2 + p * 50 + 48);
            fma2(acc[12], xin2, w48);
        }
    }
    __syncthreads();   // all reads of sInT done before overwrite

    // writeback into transposed layout (disjoint (q, pair) ranges per warp)
#pragma unroll
    for (int u = 0; u < 12; u++)
        *(unsigned long long*)&sInT[(q0 + u) * 130 + 2 * pair] = acc[u];
    if (lastq) *(unsigned long long*)&sInT[48 * 130 + 2 * pair] = acc[12];
    __syncthreads();

    // coalesced store
    if (t < 224) {
        const int w = t % 112;
        const int hh = t / 112;
        const int pcol = w / 7, pc = w % 7;
#pragma unroll
        for (int k = 0; k < 28; k++) {
            const int prow = hh * 4 + k / 7;
            const int pos = (k % 7) * 7 + pc;
            dst[(hh * 28 + k) * 112 + w] = sInT[pos * 130 + prow * 16 + pcol];
        }
    }
}

// ---------------- launcher ----------------
extern "C" void kernel_launch(void* const* d_in, const int* in_sizes, int n_in,
                              void* d_out, int out_size) {
    const float* inp    = (const float*)d_in[0];  // (16,64,112,112)
    const float* logits = (const float*)d_in[1];  // (16,100,112,112)
    const float* sigx   = (const float*)d_in[2];  // (100)
    const float* sigy   = (const float*)d_in[3];  // (100)
    const float* opac   = (const float*)d_in[4];  // (100,1) flat
    const float* rho    = (const float*)d_in[5];  // (100,1) flat
    float* out = (float*)d_out;                   // (16,8,112,112)

    k_reduce<<<3200, 196>>>(logits);
    k_params<<<49, 256>>>(sigx, sigy, opac, rho);
    k_apply<<<256, 256>>>(inp, out);
}